// round 14
// baseline (speedup 1.0000x reference)
#include <cuda_runtime.h>
#include <math.h>

#define MAXN 102400
#define MAXE 1605632
#define NBMAX 64
#define NBLK 148
#define EPT  11    // 148*1024*11 = 1,667,072 >= E

// ---------------- device scratch (zero-initialized at module load) -----------
__device__ int    g_cnt[MAXN];           // per-row counts (re-zeroed in scan phase)
__device__ float  g_deg[MAXN];           // weighted degree (re-zeroed in finalize)
__device__ int    g_rowptr[MAXN + 1];    // block-local exclusive starts
__device__ int    g_bsums[NBMAX];
__device__ int    g_boffs[NBMAX];
__device__ int    g_rps[MAXN + 1];       // GLOBAL row starts
__device__ int2   g_csr[MAXE];           // (col, ew*dinv[col] bits after phase 6)
__device__ float4 g_A4[MAXN * 4];        // xp0 - xp1
__device__ float4 g_B4[MAXN * 4];        // xp1 (raw; layer-1 gather target)
__device__ float  g_self[MAXN * 32];     // h@(W20-W21) + b2   (layer-2 self term)
__device__ float  g_z[MAXN * 32];        // h@W21 (raw; layer-2 gather target)
__device__ float  g_dinv[MAXN];

// ---------------- software grid barrier (all 148 blocks resident) ------------
__device__ int          g_bar_cnt;
__device__ volatile int g_bar_gen;

__device__ __forceinline__ void grid_sync() {
    __syncthreads();
    if (threadIdx.x == 0) {
        int gen = g_bar_gen;
        __threadfence();
        if (atomicAdd(&g_bar_cnt, 1) == NBLK - 1) {
            g_bar_cnt = 0;
            __threadfence();
            g_bar_gen = gen + 1;
        } else {
            while (g_bar_gen == gen) { __nanosleep(64); }
        }
    }
    __syncthreads();
}

// ---------------- helpers -----------------------------------------------------
__device__ __forceinline__ int detect_is64(const int* w) {
    int bad = 0;
    #pragma unroll
    for (int j = 1; j < 128; j += 2) bad |= w[j];
    return bad == 0;
}

__device__ __forceinline__ unsigned long long pack_f2(float lo, float hi) {
    unsigned long long r;
    asm("mov.b64 %0, {%1, %2};" : "=l"(r) : "r"(__float_as_uint(lo)), "r"(__float_as_uint(hi)));
    return r;
}
__device__ __forceinline__ float f2_lo(unsigned long long v) {
    unsigned int lo, hi;
    asm("mov.b64 {%0, %1}, %2;" : "=r"(lo), "=r"(hi) : "l"(v));
    return __uint_as_float(lo);
}
__device__ __forceinline__ float f2_hi(unsigned long long v) {
    unsigned int lo, hi;
    asm("mov.b64 {%0, %1}, %2;" : "=r"(lo), "=r"(hi) : "l"(v));
    return __uint_as_float(hi);
}
#define FFMA2(acc, b, w) asm("fma.rn.f32x2 %0, %1, %2, %0;" : "+l"(acc) : "l"(b), "l"(w))

// ---------------- k_build: count+rank | scan | scatter | dinv | fold ---------
__global__ void __launch_bounds__(1024, 1) k_build(const void* __restrict__ ei,
                                                   const float* __restrict__ ew,
                                                   int N, int E, int NB) {
    __shared__ int s_is64;
    __shared__ int warpSums[32];
    __shared__ int s_boffs[NBMAX];
    int t = threadIdx.x;
    if (t == 0) s_is64 = detect_is64((const int*)ei);
    __syncthreads();
    int is64 = s_is64;

    // ---- phase 1: count + rank (edges held in registers) ----
    int rr[EPT];
    int rk[EPT];
    int base_e = blockIdx.x * (1024 * EPT) + t;
    #pragma unroll
    for (int i = 0; i < EPT; i++) {
        int e = base_e + i * 1024;
        rr[i] = -1;
        if (e < E) {
            int rv = is64 ? (int)((const long long*)ei)[e] : ((const int*)ei)[e];
            rr[i] = rv;
            rk[i] = atomicAdd(&g_cnt[rv], 1);
        }
    }
    grid_sync();

    // ---- phase 2: per-block local scan (blocks 0..NB-1), reset g_cnt ----
    if (blockIdx.x < (unsigned)NB) {
        int base = blockIdx.x * 2048;
        int i0 = base + 2 * t, i1 = i0 + 1;
        int v0 = (i0 < N) ? g_cnt[i0] : 0;
        int v1 = (i1 < N) ? g_cnt[i1] : 0;
        if (i0 < N) g_cnt[i0] = 0;
        if (i1 < N) g_cnt[i1] = 0;
        int s = v0 + v1;
        int lane = t & 31, wid = t >> 5;
        int incl = s;
        #pragma unroll
        for (int d = 1; d < 32; d <<= 1) {
            int n = __shfl_up_sync(0xffffffffu, incl, d);
            if (lane >= d) incl += n;
        }
        if (lane == 31) warpSums[wid] = incl;
        __syncthreads();
        if (wid == 0) {
            int ws = warpSums[lane];
            int wi = ws;
            #pragma unroll
            for (int d = 1; d < 32; d <<= 1) {
                int n = __shfl_up_sync(0xffffffffu, wi, d);
                if (lane >= d) wi += n;
            }
            warpSums[lane] = wi - ws;
        }
        __syncthreads();
        int excl = warpSums[wid] + incl - s;
        if (i0 < N) g_rowptr[i0] = excl;
        if (i1 < N) g_rowptr[i1] = excl + v0;
        if (t == 1023) g_bsums[blockIdx.x] = warpSums[wid] + incl;
    }
    grid_sync();

    // ---- phase 3: block 0 scans the NB block sums -> g_boffs ----
    if (blockIdx.x == 0 && t < 32) {
        int lane = t;
        int b0 = (lane < NB) ? g_bsums[lane] : 0;
        int b1 = (lane + 32 < NB) ? g_bsums[lane + 32] : 0;
        int i0s = b0;
        #pragma unroll
        for (int d = 1; d < 32; d <<= 1) {
            int n = __shfl_up_sync(0xffffffffu, i0s, d);
            if (lane >= d) i0s += n;
        }
        int tot0 = __shfl_sync(0xffffffffu, i0s, 31);
        int i1s = b1;
        #pragma unroll
        for (int d = 1; d < 32; d <<= 1) {
            int n = __shfl_up_sync(0xffffffffu, i1s, d);
            if (lane >= d) i1s += n;
        }
        i1s += tot0;
        g_boffs[lane]      = i0s - b0;
        g_boffs[lane + 32] = i1s - b1;
    }
    grid_sync();

    // ---- phase 4: write g_rps + scatter (plain ew) + deg REDG ----
    if (t < NBMAX) s_boffs[t] = g_boffs[t];
    __syncthreads();
    for (int i = blockIdx.x * 1024 + t; i < N; i += NBLK * 1024)
        g_rps[i] = g_rowptr[i] + s_boffs[i >> 11];
    if (blockIdx.x == 0 && t == 0) g_rps[N] = E;

    int pp[EPT];
    #pragma unroll
    for (int i = 0; i < EPT; i++) {
        int e = base_e + i * 1024;
        pp[i] = -1;
        if (rr[i] >= 0) {
            int c = is64 ? (int)((const long long*)ei)[(long)E + e]
                         : ((const int*)ei)[E + e];
            float w = ew[e];
            int p = g_rowptr[rr[i]] + s_boffs[rr[i] >> 11] + rk[i];
            pp[i] = p;
            g_csr[p] = make_int2(c, __float_as_int(w));
            atomicAdd(&g_deg[rr[i]], w);     // REDG, no return
        }
    }
    grid_sync();

    // ---- phase 5: finalize dinv, reset deg ----
    for (int i = blockIdx.x * 1024 + t; i < N; i += NBLK * 1024) {
        float d = g_deg[i];
        g_dinv[i] = (d > 0.f) ? rsqrtf(d) : 0.f;
        g_deg[i] = 0.f;
    }
    grid_sync();

    // ---- phase 6: fold dinv[col] into csr weights (own entries) ----
    #pragma unroll
    for (int i = 0; i < EPT; i++) {
        if (pp[i] >= 0) {
            int2 v = g_csr[pp[i]];
            float wn = __int_as_float(v.y) * g_dinv[v.x];
            g_csr[pp[i]].y = __float_as_int(wn);
        }
    }
}

// ---------------- GEMM1 (FFMA2, 512 thr): A = x@W0 - x@W1, B = x@W1 ----------
// Independent of the CSR build (no dinv) -> runs on the forked graph branch.
__global__ void __launch_bounds__(512) k_gemm1(const float* __restrict__ x,
                        const float* __restrict__ W0,
                        const float* __restrict__ W1, int N) {
    __shared__ float Wsh[128 * 32];                      // 16 KB
    __shared__ unsigned long long xs2[16][2][128];       // 32 KB
    int t = threadIdx.x;
    for (int i = t; i < 128 * 16; i += 512) {
        int k = i >> 4, j = i & 15;
        Wsh[k * 32 + j]      = W0[i];
        Wsh[k * 32 + 16 + j] = W1[i];
    }
    int warp = t >> 5, lane = t & 31;
    int base = (blockIdx.x * 16 + warp) * 4;

    #pragma unroll
    for (int p = 0; p < 2; p++) {
        int n0 = base + 2 * p, n1 = n0 + 1;
        const float* x0 = x + (size_t)n0 * 128;
        const float* x1 = x + (size_t)n1 * 128;
        #pragma unroll
        for (int i = 0; i < 4; i++) {
            float fa = (n0 < N) ? x0[i * 32 + lane] : 0.f;
            float fb = (n1 < N) ? x1[i * 32 + lane] : 0.f;
            xs2[warp][p][i * 32 + lane] = pack_f2(fa, fb);
        }
    }
    __syncthreads();

    unsigned long long acc0 = 0ull, acc1 = 0ull;
    #pragma unroll 16
    for (int k = 0; k < 128; k++) {
        float wk = Wsh[k * 32 + lane];
        unsigned long long w2 = pack_f2(wk, wk);
        unsigned long long b0 = xs2[warp][0][k];
        unsigned long long b1 = xs2[warp][1][k];
        FFMA2(acc0, b0, w2);
        FFMA2(acc1, b1, w2);
    }

    float* A = (float*)g_A4;
    float* B = (float*)g_B4;
    float accs[4] = { f2_lo(acc0), f2_hi(acc0), f2_lo(acc1), f2_hi(acc1) };
    #pragma unroll
    for (int n = 0; n < 4; n++) {
        int nd = base + n;
        float a = accs[n];
        float o = __shfl_xor_sync(0xffffffffu, a, 16);
        if (nd < N) {
            if (lane < 16) A[(size_t)nd * 16 + lane] = a - o;   // xp0 - xp1
            else           B[(size_t)nd * 16 + (lane - 16)] = a; // xp1 raw
        }
    }
}

// ---------------- layer1: slot-parallel gather + register-GEMV epilogue ------
__global__ void __launch_bounds__(512, 2) k_layer1(const float* __restrict__ b1,
                         const float* __restrict__ W20,
                         const float* __restrict__ W21,
                         const float* __restrict__ b2, int N) {
    int lane = threadIdx.x & 31;
    int q = lane & 3, slot = lane >> 2;

    float wd[16], wb[16];
    #pragma unroll
    for (int k = 0; k < 16; k++) {
        float w1v = __ldg(&W21[k * 32 + lane]);
        wd[k] = __ldg(&W20[k * 32 + lane]) - w1v;
        wb[k] = w1v;
    }
    float b2v = __ldg(&b2[lane]);
    float4 bb = make_float4(0.f, 0.f, 0.f, 0.f);
    if (lane < 4) bb = ((const float4*)b1)[lane];

    int warp_g = (blockIdx.x * blockDim.x + threadIdx.x) >> 5;
    int nwarps = (gridDim.x * blockDim.x) >> 5;

    for (int row = warp_g; row < N; row += nwarps) {
        int s = g_rps[row];
        int e = g_rps[row + 1];
        float4 acc = make_float4(0.f, 0.f, 0.f, 0.f);
        for (int p = s + slot; p < e; p += 8) {
            int2 ce = g_csr[p];
            float nv = __int_as_float(ce.y);
            float4 v = g_B4[(size_t)ce.x * 4 + q];
            acc.x = fmaf(nv, v.x, acc.x);
            acc.y = fmaf(nv, v.y, acc.y);
            acc.z = fmaf(nv, v.z, acc.z);
            acc.w = fmaf(nv, v.w, acc.w);
        }
        #pragma unroll
        for (int d = 4; d < 32; d <<= 1) {
            acc.x += __shfl_xor_sync(0xffffffffu, acc.x, d);
            acc.y += __shfl_xor_sync(0xffffffffu, acc.y, d);
            acc.z += __shfl_xor_sync(0xffffffffu, acc.z, d);
            acc.w += __shfl_xor_sync(0xffffffffu, acc.w, d);
        }
        float dv = g_dinv[row];
        float4 hv = make_float4(0.f, 0.f, 0.f, 0.f);
        if (lane < 4) {
            float4 A = g_A4[(size_t)row * 4 + lane];
            hv.x = fmaxf(A.x + dv * acc.x + bb.x, 0.f);
            hv.y = fmaxf(A.y + dv * acc.y + bb.y, 0.f);
            hv.z = fmaxf(A.z + dv * acc.z + bb.z, 0.f);
            hv.w = fmaxf(A.w + dv * acc.w + bb.w, 0.f);
        }
        float self = 0.f, zz = 0.f;
        #pragma unroll
        for (int k = 0; k < 16; k++) {
            int src = k >> 2;
            float comp;
            if ((k & 3) == 0)      comp = hv.x;
            else if ((k & 3) == 1) comp = hv.y;
            else if ((k & 3) == 2) comp = hv.z;
            else                   comp = hv.w;
            float hf = __shfl_sync(0xffffffffu, comp, src);
            self = fmaf(hf, wd[k], self);
            zz   = fmaf(hf, wb[k], zz);
        }
        g_self[(size_t)row * 32 + lane] = self + b2v;
        g_z[(size_t)row * 32 + lane]    = zz;          // raw (dinv folded in csr)
    }
}

// ---------------- layer2: slot-parallel agg(z) + log_softmax -----------------
__global__ void __launch_bounds__(512) k_layer2(float* __restrict__ out, int N) {
    int gt = blockIdx.x * blockDim.x + threadIdx.x;
    int row = gt >> 5;
    if (row >= N) return;
    int lane = gt & 31;
    int q = lane & 7, slot = lane >> 3;
    int s = g_rps[row];
    int e = g_rps[row + 1];
    const float4* Z = (const float4*)g_z;
    float4 acc = make_float4(0.f, 0.f, 0.f, 0.f);
    for (int p = s + slot; p < e; p += 4) {
        int2 ce = g_csr[p];
        float nv = __int_as_float(ce.y);
        float4 v = Z[(size_t)ce.x * 8 + q];
        acc.x = fmaf(nv, v.x, acc.x);
        acc.y = fmaf(nv, v.y, acc.y);
        acc.z = fmaf(nv, v.z, acc.z);
        acc.w = fmaf(nv, v.w, acc.w);
    }
    #pragma unroll
    for (int d = 8; d < 32; d <<= 1) {
        acc.x += __shfl_xor_sync(0xffffffffu, acc.x, d);
        acc.y += __shfl_xor_sync(0xffffffffu, acc.y, d);
        acc.z += __shfl_xor_sync(0xffffffffu, acc.z, d);
        acc.w += __shfl_xor_sync(0xffffffffu, acc.w, d);
    }
    float dv = g_dinv[row];
    float4 sv = ((const float4*)g_self)[(size_t)row * 8 + q];
    float4 val;
    val.x = sv.x + dv * acc.x;
    val.y = sv.y + dv * acc.y;
    val.z = sv.z + dv * acc.z;
    val.w = sv.w + dv * acc.w;

    float m = fmaxf(fmaxf(val.x, val.y), fmaxf(val.z, val.w));
    #pragma unroll
    for (int d = 1; d < 8; d <<= 1) m = fmaxf(m, __shfl_xor_sync(0xffffffffu, m, d));
    float sum = __expf(val.x - m) + __expf(val.y - m)
              + __expf(val.z - m) + __expf(val.w - m);
    #pragma unroll
    for (int d = 1; d < 8; d <<= 1) sum += __shfl_xor_sync(0xffffffffu, sum, d);
    float ls = m + __logf(sum);
    if (lane < 8) {
        float4 o;
        o.x = val.x - ls; o.y = val.y - ls; o.z = val.z - ls; o.w = val.w - ls;
        ((float4*)out)[(size_t)row * 8 + q] = o;
    }
}

// ---------------- launcher: forked capture branch for gemm1 ------------------
extern "C" void kernel_launch(void* const* d_in, const int* in_sizes, int n_in,
                              void* d_out, int out_size) {
    const float* x   = (const float*)d_in[0];
    const void*  ei  = d_in[1];
    const float* ew  = (const float*)d_in[2];
    const float* W10 = (const float*)d_in[3];
    const float* W11 = (const float*)d_in[4];
    const float* b1  = (const float*)d_in[5];
    const float* W20 = (const float*)d_in[6];
    const float* W21 = (const float*)d_in[7];
    const float* b2  = (const float*)d_in[8];
    float* out = (float*)d_out;

    int N = in_sizes[0] / 128;
    int E = in_sizes[2];
    int NB = (N + 2047) / 2048;

    cudaStream_t s2;
    cudaEvent_t ev1, ev2;
    bool forked = (cudaStreamCreateWithFlags(&s2, cudaStreamNonBlocking) == cudaSuccess);
    if (forked) {
        cudaEventCreateWithFlags(&ev1, cudaEventDisableTiming);
        cudaEventCreateWithFlags(&ev2, cudaEventDisableTiming);
        cudaEventRecord(ev1, 0);
        cudaStreamWaitEvent(s2, ev1, 0);
        k_gemm1<<<(N + 63) / 64, 512, 0, s2>>>(x, W10, W11, N);   // parallel branch
        cudaEventRecord(ev2, s2);
    }

    k_build<<<NBLK, 1024>>>(ei, ew, N, E, NB);

    if (forked) {
        cudaStreamWaitEvent(0, ev2, 0);   // join before layer1
    } else {
        k_gemm1<<<(N + 63) / 64, 512>>>(x, W10, W11, N);  // serial fallback
    }

    k_layer1<<<296, 512>>>(b1, W20, W21, b2, N);
    k_layer2<<<(N * 32 + 511) / 512, 512>>>(out, N);
    // streams/events intentionally not destroyed: destroying capture-joined
    // objects mid-capture can invalidate the graph; leak is bounded (2 calls).
}

// round 15
// speedup vs baseline: 1.2044x; 1.2044x over previous
#include <cuda_runtime.h>
#include <math.h>

#define MAXN 102400
#define MAXE 1605632
#define NBMAX 64
#define NBLK 148
#define EPT  11    // 148*1024*11 = 1,667,072 >= E

// ---------------- device scratch (zero-initialized at module load) -----------
__device__ int    g_cnt[MAXN];           // per-row counts (re-zeroed in scan phase)
__device__ float  g_deg[MAXN];           // weighted degree (re-zeroed in finalize)
__device__ int    g_rowptr[MAXN + 1];    // block-local exclusive starts
__device__ int    g_bsums[NBMAX];
__device__ int    g_boffs[NBMAX];
__device__ int    g_rps[MAXN + 1];       // GLOBAL row starts
__device__ int2   g_csr[MAXE];           // (col, ew bits)
__device__ float4 g_A4[MAXN * 4];        // xp0 - xp1
__device__ float4 g_B4[MAXN * 4];        // dinv * xp1 (layer-1 gather target)
__device__ float  g_self[MAXN * 32];     // h@(W20-W21) + b2   (layer-2 self term)
__device__ float  g_z[MAXN * 32];        // dinv * (h@W21)     (layer-2 gather target)
__device__ float  g_dinv[MAXN];

// ---------------- software grid barrier (all 148 blocks resident) ------------
__device__ int          g_bar_cnt;
__device__ volatile int g_bar_gen;

__device__ __forceinline__ void grid_sync() {
    __syncthreads();
    if (threadIdx.x == 0) {
        int gen = g_bar_gen;
        __threadfence();
        if (atomicAdd(&g_bar_cnt, 1) == NBLK - 1) {
            g_bar_cnt = 0;
            __threadfence();
            g_bar_gen = gen + 1;
        } else {
            while (g_bar_gen == gen) { __nanosleep(64); }
        }
    }
    __syncthreads();
}

// ---------------- helpers -----------------------------------------------------
__device__ __forceinline__ int detect_is64(const int* w) {
    int bad = 0;
    #pragma unroll
    for (int j = 1; j < 128; j += 2) bad |= w[j];
    return bad == 0;
}

__device__ __forceinline__ unsigned long long pack_f2(float lo, float hi) {
    unsigned long long r;
    asm("mov.b64 %0, {%1, %2};" : "=l"(r) : "r"(__float_as_uint(lo)), "r"(__float_as_uint(hi)));
    return r;
}
__device__ __forceinline__ float f2_lo(unsigned long long v) {
    unsigned int lo, hi;
    asm("mov.b64 {%0, %1}, %2;" : "=r"(lo), "=r"(hi) : "l"(v));
    return __uint_as_float(lo);
}
__device__ __forceinline__ float f2_hi(unsigned long long v) {
    unsigned int lo, hi;
    asm("mov.b64 {%0, %1}, %2;" : "=r"(lo), "=r"(hi) : "l"(v));
    return __uint_as_float(hi);
}
#define FFMA2(acc, b, w) asm("fma.rn.f32x2 %0, %1, %2, %0;" : "+l"(acc) : "l"(b), "l"(w))

// ---------------- k_build: count+rank | scan | scatter | dinv (one kernel) ---
__global__ void __launch_bounds__(1024, 1) k_build(const void* __restrict__ ei,
                                                   const float* __restrict__ ew,
                                                   int N, int E, int NB) {
    __shared__ int s_is64;
    __shared__ int warpSums[32];
    __shared__ int s_boffs[NBMAX];
    int t = threadIdx.x;
    if (t == 0) s_is64 = detect_is64((const int*)ei);
    __syncthreads();
    int is64 = s_is64;

    // ---- phase 1: count + rank (edges held in registers) ----
    int rr[EPT];
    int rk[EPT];
    int base_e = blockIdx.x * (1024 * EPT) + t;
    #pragma unroll
    for (int i = 0; i < EPT; i++) {
        int e = base_e + i * 1024;
        rr[i] = -1;
        if (e < E) {
            int rv = is64 ? (int)((const long long*)ei)[e] : ((const int*)ei)[e];
            rr[i] = rv;
            rk[i] = atomicAdd(&g_cnt[rv], 1);
        }
    }
    grid_sync();

    // ---- phase 2: per-block local scan (blocks 0..NB-1), reset g_cnt ----
    if (blockIdx.x < (unsigned)NB) {
        int base = blockIdx.x * 2048;
        int i0 = base + 2 * t, i1 = i0 + 1;
        int v0 = (i0 < N) ? g_cnt[i0] : 0;
        int v1 = (i1 < N) ? g_cnt[i1] : 0;
        if (i0 < N) g_cnt[i0] = 0;
        if (i1 < N) g_cnt[i1] = 0;
        int s = v0 + v1;
        int lane = t & 31, wid = t >> 5;
        int incl = s;
        #pragma unroll
        for (int d = 1; d < 32; d <<= 1) {
            int n = __shfl_up_sync(0xffffffffu, incl, d);
            if (lane >= d) incl += n;
        }
        if (lane == 31) warpSums[wid] = incl;
        __syncthreads();
        if (wid == 0) {
            int ws = warpSums[lane];
            int wi = ws;
            #pragma unroll
            for (int d = 1; d < 32; d <<= 1) {
                int n = __shfl_up_sync(0xffffffffu, wi, d);
                if (lane >= d) wi += n;
            }
            warpSums[lane] = wi - ws;
        }
        __syncthreads();
        int excl = warpSums[wid] + incl - s;
        if (i0 < N) g_rowptr[i0] = excl;
        if (i1 < N) g_rowptr[i1] = excl + v0;
        if (t == 1023) g_bsums[blockIdx.x] = warpSums[wid] + incl;
    }
    grid_sync();

    // ---- phase 3: block 0 scans the NB block sums -> g_boffs ----
    if (blockIdx.x == 0 && t < 32) {
        int lane = t;
        int b0 = (lane < NB) ? g_bsums[lane] : 0;
        int b1 = (lane + 32 < NB) ? g_bsums[lane + 32] : 0;
        int i0s = b0;
        #pragma unroll
        for (int d = 1; d < 32; d <<= 1) {
            int n = __shfl_up_sync(0xffffffffu, i0s, d);
            if (lane >= d) i0s += n;
        }
        int tot0 = __shfl_sync(0xffffffffu, i0s, 31);
        int i1s = b1;
        #pragma unroll
        for (int d = 1; d < 32; d <<= 1) {
            int n = __shfl_up_sync(0xffffffffu, i1s, d);
            if (lane >= d) i1s += n;
        }
        i1s += tot0;
        g_boffs[lane]      = i0s - b0;
        g_boffs[lane + 32] = i1s - b1;
    }
    grid_sync();

    // ---- phase 4: write g_rps + scatter from registers + deg REDG ----
    if (t < NBMAX) s_boffs[t] = g_boffs[t];
    __syncthreads();
    for (int i = blockIdx.x * 1024 + t; i < N; i += NBLK * 1024)
        g_rps[i] = g_rowptr[i] + s_boffs[i >> 11];
    if (blockIdx.x == 0 && t == 0) g_rps[N] = E;

    #pragma unroll
    for (int i = 0; i < EPT; i++) {
        int e = base_e + i * 1024;
        if (rr[i] >= 0) {
            int c = is64 ? (int)((const long long*)ei)[(long)E + e]
                         : ((const int*)ei)[E + e];
            float w = ew[e];
            int p = g_rowptr[rr[i]] + s_boffs[rr[i] >> 11] + rk[i];
            g_csr[p] = make_int2(c, __float_as_int(w));
            atomicAdd(&g_deg[rr[i]], w);     // REDG, no return
        }
    }
    grid_sync();

    // ---- phase 5: finalize dinv, reset deg ----
    for (int i = blockIdx.x * 1024 + t; i < N; i += NBLK * 1024) {
        float d = g_deg[i];
        g_dinv[i] = (d > 0.f) ? rsqrtf(d) : 0.f;
        g_deg[i] = 0.f;
    }
}

// ---------------- GEMM1 (FFMA2, 512 thr): A = x@W0 - x@W1, B = dinv*(x@W1) ---
__global__ void __launch_bounds__(512) k_gemm1(const float* __restrict__ x,
                        const float* __restrict__ W0,
                        const float* __restrict__ W1, int N) {
    __shared__ float Wsh[128 * 32];                      // 16 KB
    __shared__ unsigned long long xs2[16][2][128];       // 32 KB
    int t = threadIdx.x;
    for (int i = t; i < 128 * 16; i += 512) {
        int k = i >> 4, j = i & 15;
        Wsh[k * 32 + j]      = W0[i];
        Wsh[k * 32 + 16 + j] = W1[i];
    }
    int warp = t >> 5, lane = t & 31;
    int base = (blockIdx.x * 16 + warp) * 4;

    #pragma unroll
    for (int p = 0; p < 2; p++) {
        int n0 = base + 2 * p, n1 = n0 + 1;
        const float* x0 = x + (size_t)n0 * 128;
        const float* x1 = x + (size_t)n1 * 128;
        #pragma unroll
        for (int i = 0; i < 4; i++) {
            float fa = (n0 < N) ? x0[i * 32 + lane] : 0.f;
            float fb = (n1 < N) ? x1[i * 32 + lane] : 0.f;
            xs2[warp][p][i * 32 + lane] = pack_f2(fa, fb);
        }
    }
    __syncthreads();

    unsigned long long acc0 = 0ull, acc1 = 0ull;
    #pragma unroll 16
    for (int k = 0; k < 128; k++) {
        float wk = Wsh[k * 32 + lane];
        unsigned long long w2 = pack_f2(wk, wk);
        unsigned long long b0 = xs2[warp][0][k];
        unsigned long long b1 = xs2[warp][1][k];
        FFMA2(acc0, b0, w2);
        FFMA2(acc1, b1, w2);
    }

    float* A = (float*)g_A4;
    float* B = (float*)g_B4;
    float accs[4] = { f2_lo(acc0), f2_hi(acc0), f2_lo(acc1), f2_hi(acc1) };
    #pragma unroll
    for (int n = 0; n < 4; n++) {
        int nd = base + n;
        float a = accs[n];
        float o = __shfl_xor_sync(0xffffffffu, a, 16);
        if (nd < N) {
            if (lane < 16) A[(size_t)nd * 16 + lane] = a - o;   // xp0 - xp1
            else           B[(size_t)nd * 16 + (lane - 16)] = g_dinv[nd] * a;
        }
    }
}

// ---------------- layer1: slot-parallel gather (unroll x2) + reg-GEMV --------
// warp per row (grid-stride). q=lane&3, slot=lane>>2: 8 edges in flight,
// unroll x2 with dual accumulators -> 16 outstanding loads per warp.
__global__ void __launch_bounds__(512, 2) k_layer1(const float* __restrict__ b1,
                         const float* __restrict__ W20,
                         const float* __restrict__ W21,
                         const float* __restrict__ b2, int N) {
    int lane = threadIdx.x & 31;
    int q = lane & 3, slot = lane >> 2;

    float wd[16], wb[16];
    #pragma unroll
    for (int k = 0; k < 16; k++) {
        float w1v = __ldg(&W21[k * 32 + lane]);
        wd[k] = __ldg(&W20[k * 32 + lane]) - w1v;
        wb[k] = w1v;
    }
    float b2v = __ldg(&b2[lane]);
    float4 bb = make_float4(0.f, 0.f, 0.f, 0.f);
    if (lane < 4) bb = ((const float4*)b1)[lane];

    int warp_g = (blockIdx.x * blockDim.x + threadIdx.x) >> 5;
    int nwarps = (gridDim.x * blockDim.x) >> 5;

    for (int row = warp_g; row < N; row += nwarps) {
        int s = g_rps[row];
        int e = g_rps[row + 1];
        float4 acc = make_float4(0.f, 0.f, 0.f, 0.f);
        float4 acd = make_float4(0.f, 0.f, 0.f, 0.f);
        int p = s + slot;
        for (; p + 8 < e; p += 16) {              // 2 edges/thread/iter
            int2 ca = g_csr[p];
            int2 cb = g_csr[p + 8];
            float na = __int_as_float(ca.y);
            float nb = __int_as_float(cb.y);
            float4 va = g_B4[(size_t)ca.x * 4 + q];
            float4 vb = g_B4[(size_t)cb.x * 4 + q];
            acc.x = fmaf(na, va.x, acc.x);
            acc.y = fmaf(na, va.y, acc.y);
            acc.z = fmaf(na, va.z, acc.z);
            acc.w = fmaf(na, va.w, acc.w);
            acd.x = fmaf(nb, vb.x, acd.x);
            acd.y = fmaf(nb, vb.y, acd.y);
            acd.z = fmaf(nb, vb.z, acd.z);
            acd.w = fmaf(nb, vb.w, acd.w);
        }
        if (p < e) {
            int2 ca = g_csr[p];
            float na = __int_as_float(ca.y);
            float4 va = g_B4[(size_t)ca.x * 4 + q];
            acc.x = fmaf(na, va.x, acc.x);
            acc.y = fmaf(na, va.y, acc.y);
            acc.z = fmaf(na, va.z, acc.z);
            acc.w = fmaf(na, va.w, acc.w);
        }
        acc.x += acd.x; acc.y += acd.y; acc.z += acd.z; acc.w += acd.w;
        #pragma unroll
        for (int d = 4; d < 32; d <<= 1) {
            acc.x += __shfl_xor_sync(0xffffffffu, acc.x, d);
            acc.y += __shfl_xor_sync(0xffffffffu, acc.y, d);
            acc.z += __shfl_xor_sync(0xffffffffu, acc.z, d);
            acc.w += __shfl_xor_sync(0xffffffffu, acc.w, d);
        }
        float dv = g_dinv[row];
        float4 hv = make_float4(0.f, 0.f, 0.f, 0.f);
        if (lane < 4) {
            float4 A = g_A4[(size_t)row * 4 + lane];
            hv.x = fmaxf(A.x + dv * acc.x + bb.x, 0.f);
            hv.y = fmaxf(A.y + dv * acc.y + bb.y, 0.f);
            hv.z = fmaxf(A.z + dv * acc.z + bb.z, 0.f);
            hv.w = fmaxf(A.w + dv * acc.w + bb.w, 0.f);
        }
        float self = 0.f, zz = 0.f;
        #pragma unroll
        for (int k = 0; k < 16; k++) {
            int src = k >> 2;
            float comp;
            if ((k & 3) == 0)      comp = hv.x;
            else if ((k & 3) == 1) comp = hv.y;
            else if ((k & 3) == 2) comp = hv.z;
            else                   comp = hv.w;
            float hf = __shfl_sync(0xffffffffu, comp, src);
            self = fmaf(hf, wd[k], self);
            zz   = fmaf(hf, wb[k], zz);
        }
        g_self[(size_t)row * 32 + lane] = self + b2v;
        g_z[(size_t)row * 32 + lane]    = dv * zz;
    }
}

// ---------------- layer2: slot-parallel agg(z) (unroll x2) + log_softmax -----
// warp per row. q=lane&7, slot=lane>>3: 4 edges in flight, unroll x2 with
// dual accumulators -> 8 outstanding 128B row loads per warp.
__global__ void __launch_bounds__(512) k_layer2(float* __restrict__ out, int N) {
    int gt = blockIdx.x * blockDim.x + threadIdx.x;
    int row = gt >> 5;
    if (row >= N) return;
    int lane = gt & 31;
    int q = lane & 7, slot = lane >> 3;
    int s = g_rps[row];
    int e = g_rps[row + 1];
    const float4* Z = (const float4*)g_z;
    float4 acc = make_float4(0.f, 0.f, 0.f, 0.f);
    float4 acd = make_float4(0.f, 0.f, 0.f, 0.f);
    int p = s + slot;
    for (; p + 4 < e; p += 8) {                   // 2 edges/thread/iter
        int2 ca = g_csr[p];
        int2 cb = g_csr[p + 4];
        float na = __int_as_float(ca.y);
        float nb = __int_as_float(cb.y);
        float4 va = Z[(size_t)ca.x * 8 + q];
        float4 vb = Z[(size_t)cb.x * 8 + q];
        acc.x = fmaf(na, va.x, acc.x);
        acc.y = fmaf(na, va.y, acc.y);
        acc.z = fmaf(na, va.z, acc.z);
        acc.w = fmaf(na, va.w, acc.w);
        acd.x = fmaf(nb, vb.x, acd.x);
        acd.y = fmaf(nb, vb.y, acd.y);
        acd.z = fmaf(nb, vb.z, acd.z);
        acd.w = fmaf(nb, vb.w, acd.w);
    }
    if (p < e) {
        int2 ca = g_csr[p];
        float na = __int_as_float(ca.y);
        float4 va = Z[(size_t)ca.x * 8 + q];
        acc.x = fmaf(na, va.x, acc.x);
        acc.y = fmaf(na, va.y, acc.y);
        acc.z = fmaf(na, va.z, acc.z);
        acc.w = fmaf(na, va.w, acc.w);
    }
    acc.x += acd.x; acc.y += acd.y; acc.z += acd.z; acc.w += acd.w;
    #pragma unroll
    for (int d = 8; d < 32; d <<= 1) {
        acc.x += __shfl_xor_sync(0xffffffffu, acc.x, d);
        acc.y += __shfl_xor_sync(0xffffffffu, acc.y, d);
        acc.z += __shfl_xor_sync(0xffffffffu, acc.z, d);
        acc.w += __shfl_xor_sync(0xffffffffu, acc.w, d);
    }
    float dv = g_dinv[row];
    float4 sv = ((const float4*)g_self)[(size_t)row * 8 + q];
    float4 val;
    val.x = sv.x + dv * acc.x;
    val.y = sv.y + dv * acc.y;
    val.z = sv.z + dv * acc.z;
    val.w = sv.w + dv * acc.w;

    float m = fmaxf(fmaxf(val.x, val.y), fmaxf(val.z, val.w));
    #pragma unroll
    for (int d = 1; d < 8; d <<= 1) m = fmaxf(m, __shfl_xor_sync(0xffffffffu, m, d));
    float sum = __expf(val.x - m) + __expf(val.y - m)
              + __expf(val.z - m) + __expf(val.w - m);
    #pragma unroll
    for (int d = 1; d < 8; d <<= 1) sum += __shfl_xor_sync(0xffffffffu, sum, d);
    float ls = m + __logf(sum);
    if (lane < 8) {
        float4 o;
        o.x = val.x - ls; o.y = val.y - ls; o.z = val.z - ls; o.w = val.w - ls;
        ((float4*)out)[(size_t)row * 8 + q] = o;
    }
}

// ---------------- launcher ----------------------------------------------------
extern "C" void kernel_launch(void* const* d_in, const int* in_sizes, int n_in,
                              void* d_out, int out_size) {
    const float* x   = (const float*)d_in[0];
    const void*  ei  = d_in[1];
    const float* ew  = (const float*)d_in[2];
    const float* W10 = (const float*)d_in[3];
    const float* W11 = (const float*)d_in[4];
    const float* b1  = (const float*)d_in[5];
    const float* W20 = (const float*)d_in[6];
    const float* W21 = (const float*)d_in[7];
    const float* b2  = (const float*)d_in[8];
    float* out = (float*)d_out;

    int N = in_sizes[0] / 128;
    int E = in_sizes[2];
    int NB = (N + 2047) / 2048;

    k_build<<<NBLK, 1024>>>(ei, ew, N, E, NB);
    k_gemm1<<<(N + 63) / 64, 512>>>(x, W10, W11, N);
    k_layer1<<<296, 512>>>(b1, W20, W21, b2, N);
    k_layer2<<<(N * 32 + 511) / 512, 512>>>(out, N);
}

// round 16
// speedup vs baseline: 1.2664x; 1.0515x over previous
#include <cuda_runtime.h>
#include <math.h>

#define MAXN 102400
#define MAXE 1605632
#define NBMAX 64
#define NBLK 148
#define EPT  11    // 148*1024*11 = 1,667,072 >= E

// ---------------- device scratch (zero-initialized at module load) -----------
__device__ int    g_cnt[MAXN];           // per-row counts (re-zeroed in scan phase)
__device__ float  g_deg[MAXN];           // weighted degree (re-zeroed in finalize)
__device__ int    g_rowptr[MAXN + 1];    // block-local exclusive starts
__device__ int    g_bsums[NBMAX];
__device__ int    g_boffs[NBMAX];
__device__ int    g_rps[MAXN + 1];       // GLOBAL row starts
__device__ int2   g_csr[MAXE];           // (col, ew bits)
__device__ float4 g_A4[MAXN * 4];        // xp0 - xp1
__device__ float4 g_B4[MAXN * 4];        // dinv * xp1 (layer-1 gather target)
__device__ float  g_self[MAXN * 32];     // h@(W20-W21) + b2   (layer-2 self term)
__device__ float  g_z[MAXN * 32];        // dinv * (h@W21)     (layer-2 gather target)
__device__ float  g_dinv[MAXN];

// ---------------- software grid barrier (all 148 blocks resident) ------------
__device__ int          g_bar_cnt;
__device__ volatile int g_bar_gen;

__device__ __forceinline__ void grid_sync() {
    __syncthreads();
    if (threadIdx.x == 0) {
        int gen = g_bar_gen;
        __threadfence();
        if (atomicAdd(&g_bar_cnt, 1) == NBLK - 1) {
            g_bar_cnt = 0;
            __threadfence();
            g_bar_gen = gen + 1;
        } else {
            while (g_bar_gen == gen) { __nanosleep(64); }
        }
    }
    __syncthreads();
}

// ---------------- helpers -----------------------------------------------------
__device__ __forceinline__ int detect_is64(const int* w) {
    int bad = 0;
    #pragma unroll
    for (int j = 1; j < 128; j += 2) bad |= w[j];
    return bad == 0;
}

__device__ __forceinline__ unsigned long long pack_f2(float lo, float hi) {
    unsigned long long r;
    asm("mov.b64 %0, {%1, %2};" : "=l"(r) : "r"(__float_as_uint(lo)), "r"(__float_as_uint(hi)));
    return r;
}
__device__ __forceinline__ float f2_lo(unsigned long long v) {
    unsigned int lo, hi;
    asm("mov.b64 {%0, %1}, %2;" : "=r"(lo), "=r"(hi) : "l"(v));
    return __uint_as_float(lo);
}
__device__ __forceinline__ float f2_hi(unsigned long long v) {
    unsigned int lo, hi;
    asm("mov.b64 {%0, %1}, %2;" : "=r"(lo), "=r"(hi) : "l"(v));
    return __uint_as_float(hi);
}
#define FFMA2(acc, b, w) asm("fma.rn.f32x2 %0, %1, %2, %0;" : "+l"(acc) : "l"(b), "l"(w))

// ---------------- k_build: count+rank | scan | scatter | dinv (one kernel) ---
__global__ void __launch_bounds__(1024, 1) k_build(const void* __restrict__ ei,
                                                   const float* __restrict__ ew,
                                                   int N, int E, int NB) {
    __shared__ int s_is64;
    __shared__ int warpSums[32];
    __shared__ int s_boffs[NBMAX];
    int t = threadIdx.x;
    if (t == 0) s_is64 = detect_is64((const int*)ei);
    __syncthreads();
    int is64 = s_is64;

    // ---- phase 1: count + rank (edges held in registers) ----
    int rr[EPT];
    int rk[EPT];
    int base_e = blockIdx.x * (1024 * EPT) + t;
    #pragma unroll
    for (int i = 0; i < EPT; i++) {
        int e = base_e + i * 1024;
        rr[i] = -1;
        if (e < E) {
            int rv = is64 ? (int)((const long long*)ei)[e] : ((const int*)ei)[e];
            rr[i] = rv;
            rk[i] = atomicAdd(&g_cnt[rv], 1);
        }
    }
    grid_sync();

    // ---- phase 2: per-block local scan (blocks 0..NB-1), reset g_cnt ----
    if (blockIdx.x < (unsigned)NB) {
        int base = blockIdx.x * 2048;
        int i0 = base + 2 * t, i1 = i0 + 1;
        int v0 = (i0 < N) ? g_cnt[i0] : 0;
        int v1 = (i1 < N) ? g_cnt[i1] : 0;
        if (i0 < N) g_cnt[i0] = 0;
        if (i1 < N) g_cnt[i1] = 0;
        int s = v0 + v1;
        int lane = t & 31, wid = t >> 5;
        int incl = s;
        #pragma unroll
        for (int d = 1; d < 32; d <<= 1) {
            int n = __shfl_up_sync(0xffffffffu, incl, d);
            if (lane >= d) incl += n;
        }
        if (lane == 31) warpSums[wid] = incl;
        __syncthreads();
        if (wid == 0) {
            int ws = warpSums[lane];
            int wi = ws;
            #pragma unroll
            for (int d = 1; d < 32; d <<= 1) {
                int n = __shfl_up_sync(0xffffffffu, wi, d);
                if (lane >= d) wi += n;
            }
            warpSums[lane] = wi - ws;
        }
        __syncthreads();
        int excl = warpSums[wid] + incl - s;
        if (i0 < N) g_rowptr[i0] = excl;
        if (i1 < N) g_rowptr[i1] = excl + v0;
        if (t == 1023) g_bsums[blockIdx.x] = warpSums[wid] + incl;
    }
    grid_sync();

    // ---- phase 3: block 0 scans the NB block sums -> g_boffs ----
    if (blockIdx.x == 0 && t < 32) {
        int lane = t;
        int b0 = (lane < NB) ? g_bsums[lane] : 0;
        int b1 = (lane + 32 < NB) ? g_bsums[lane + 32] : 0;
        int i0s = b0;
        #pragma unroll
        for (int d = 1; d < 32; d <<= 1) {
            int n = __shfl_up_sync(0xffffffffu, i0s, d);
            if (lane >= d) i0s += n;
        }
        int tot0 = __shfl_sync(0xffffffffu, i0s, 31);
        int i1s = b1;
        #pragma unroll
        for (int d = 1; d < 32; d <<= 1) {
            int n = __shfl_up_sync(0xffffffffu, i1s, d);
            if (lane >= d) i1s += n;
        }
        i1s += tot0;
        g_boffs[lane]      = i0s - b0;
        g_boffs[lane + 32] = i1s - b1;
    }
    grid_sync();

    // ---- phase 4: write g_rps + scatter from registers + deg REDG ----
    if (t < NBMAX) s_boffs[t] = g_boffs[t];
    __syncthreads();
    for (int i = blockIdx.x * 1024 + t; i < N; i += NBLK * 1024)
        g_rps[i] = g_rowptr[i] + s_boffs[i >> 11];
    if (blockIdx.x == 0 && t == 0) g_rps[N] = E;

    #pragma unroll
    for (int i = 0; i < EPT; i++) {
        int e = base_e + i * 1024;
        if (rr[i] >= 0) {
            int c = is64 ? (int)((const long long*)ei)[(long)E + e]
                         : ((const int*)ei)[E + e];
            float w = ew[e];
            int p = g_rowptr[rr[i]] + s_boffs[rr[i] >> 11] + rk[i];
            g_csr[p] = make_int2(c, __float_as_int(w));
            atomicAdd(&g_deg[rr[i]], w);     // REDG, no return
        }
    }
    grid_sync();

    // ---- phase 5: finalize dinv, reset deg ----
    for (int i = blockIdx.x * 1024 + t; i < N; i += NBLK * 1024) {
        float d = g_deg[i];
        g_dinv[i] = (d > 0.f) ? rsqrtf(d) : 0.f;
        g_deg[i] = 0.f;
    }
}

// ---------------- GEMM1 (k-paired FFMA2): A = x@W0 - x@W1, B = dinv*(x@W1) ---
// 512 thr = 16 warps x 4 nodes (2 f32x2 accumulators). W stored as f32x2 over
// (k, k+1): per 2k -> 1 LDS.64 distinct + 2 LDS.128 broadcasts (2 cyc/k total).
__global__ void __launch_bounds__(512) k_gemm1(const float* __restrict__ x,
                        const float* __restrict__ W0,
                        const float* __restrict__ W1, int N) {
    __shared__ unsigned long long Wsh2[64 * 32];                 // 16 KB
    __shared__ alignas(16) unsigned long long xs2[16][2][128];   // 32 KB
    int t = threadIdx.x;
    // Wsh2[k2*32+j] = (W[2k2][j], W[2k2+1][j]); j<16 from W0, j>=16 from W1
    for (int i = t; i < 64 * 32; i += 512) {
        int k2 = i >> 5, j = i & 31;
        float lo, hi;
        if (j < 16) { lo = W0[(2 * k2) * 16 + j];        hi = W0[(2 * k2 + 1) * 16 + j]; }
        else        { lo = W1[(2 * k2) * 16 + (j - 16)]; hi = W1[(2 * k2 + 1) * 16 + (j - 16)]; }
        Wsh2[i] = pack_f2(lo, hi);
    }
    int warp = t >> 5, lane = t & 31;
    int base = (blockIdx.x * 16 + warp) * 4;

    #pragma unroll
    for (int p = 0; p < 2; p++) {
        int n0 = base + 2 * p, n1 = n0 + 1;
        const float* x0 = x + (size_t)n0 * 128;
        const float* x1 = x + (size_t)n1 * 128;
        #pragma unroll
        for (int i = 0; i < 4; i++) {
            float fa = (n0 < N) ? x0[i * 32 + lane] : 0.f;
            float fb = (n1 < N) ? x1[i * 32 + lane] : 0.f;
            xs2[warp][p][i * 32 + lane] = pack_f2(fa, fb);
        }
    }
    __syncthreads();

    unsigned long long acc0 = 0ull, acc1 = 0ull;   // (n0,n1), (n2,n3)
    #pragma unroll 8
    for (int k2 = 0; k2 < 64; k2++) {
        unsigned long long wp = Wsh2[k2 * 32 + lane];           // LDS.64 distinct
        float wk0 = f2_lo(wp), wk1 = f2_hi(wp);
        unsigned long long w00 = pack_f2(wk0, wk0);
        unsigned long long w11 = pack_f2(wk1, wk1);
        ulonglong2 b0 = *(const ulonglong2*)&xs2[warp][0][2 * k2];  // LDS.128 bcast
        ulonglong2 b1 = *(const ulonglong2*)&xs2[warp][1][2 * k2];
        FFMA2(acc0, b0.x, w00); FFMA2(acc0, b0.y, w11);
        FFMA2(acc1, b1.x, w00); FFMA2(acc1, b1.y, w11);
    }

    float* A = (float*)g_A4;
    float* B = (float*)g_B4;
    float accs[4] = { f2_lo(acc0), f2_hi(acc0), f2_lo(acc1), f2_hi(acc1) };
    #pragma unroll
    for (int n = 0; n < 4; n++) {
        int nd = base + n;
        float a = accs[n];
        float o = __shfl_xor_sync(0xffffffffu, a, 16);
        if (nd < N) {
            if (lane < 16) A[(size_t)nd * 16 + lane] = a - o;   // xp0 - xp1
            else           B[(size_t)nd * 16 + (lane - 16)] = g_dinv[nd] * a;
        }
    }
}

// ---------------- layer1: slot-parallel gather + register-GEMV epilogue ------
// warp per row (grid-stride). q=lane&3 (float4 of B row), slot=lane>>2:
// 8 edges in flight. Epilogue: h via 16 shuffles into self/z GEMV (W2 in regs).
__global__ void __launch_bounds__(512, 2) k_layer1(const float* __restrict__ b1,
                         const float* __restrict__ W20,
                         const float* __restrict__ W21,
                         const float* __restrict__ b2, int N) {
    int lane = threadIdx.x & 31;
    int q = lane & 3, slot = lane >> 2;

    float wd[16], wb[16];
    #pragma unroll
    for (int k = 0; k < 16; k++) {
        float w1v = __ldg(&W21[k * 32 + lane]);
        wd[k] = __ldg(&W20[k * 32 + lane]) - w1v;
        wb[k] = w1v;
    }
    float b2v = __ldg(&b2[lane]);
    float4 bb = make_float4(0.f, 0.f, 0.f, 0.f);
    if (lane < 4) bb = ((const float4*)b1)[lane];

    int warp_g = (blockIdx.x * blockDim.x + threadIdx.x) >> 5;
    int nwarps = (gridDim.x * blockDim.x) >> 5;

    for (int row = warp_g; row < N; row += nwarps) {
        int s = g_rps[row];
        int e = g_rps[row + 1];
        float4 acc = make_float4(0.f, 0.f, 0.f, 0.f);
        for (int p = s + slot; p < e; p += 8) {
            int2 ce = g_csr[p];
            float nv = __int_as_float(ce.y);
            float4 v = g_B4[(size_t)ce.x * 4 + q];
            acc.x = fmaf(nv, v.x, acc.x);
            acc.y = fmaf(nv, v.y, acc.y);
            acc.z = fmaf(nv, v.z, acc.z);
            acc.w = fmaf(nv, v.w, acc.w);
        }
        #pragma unroll
        for (int d = 4; d < 32; d <<= 1) {
            acc.x += __shfl_xor_sync(0xffffffffu, acc.x, d);
            acc.y += __shfl_xor_sync(0xffffffffu, acc.y, d);
            acc.z += __shfl_xor_sync(0xffffffffu, acc.z, d);
            acc.w += __shfl_xor_sync(0xffffffffu, acc.w, d);
        }
        float dv = g_dinv[row];
        float4 hv = make_float4(0.f, 0.f, 0.f, 0.f);
        if (lane < 4) {
            float4 A = g_A4[(size_t)row * 4 + lane];
            hv.x = fmaxf(A.x + dv * acc.x + bb.x, 0.f);
            hv.y = fmaxf(A.y + dv * acc.y + bb.y, 0.f);
            hv.z = fmaxf(A.z + dv * acc.z + bb.z, 0.f);
            hv.w = fmaxf(A.w + dv * acc.w + bb.w, 0.f);
        }
        float self = 0.f, zz = 0.f;
        #pragma unroll
        for (int k = 0; k < 16; k++) {
            int src = k >> 2;
            float comp;
            if ((k & 3) == 0)      comp = hv.x;
            else if ((k & 3) == 1) comp = hv.y;
            else if ((k & 3) == 2) comp = hv.z;
            else                   comp = hv.w;
            float hf = __shfl_sync(0xffffffffu, comp, src);
            self = fmaf(hf, wd[k], self);
            zz   = fmaf(hf, wb[k], zz);
        }
        g_self[(size_t)row * 32 + lane] = self + b2v;
        g_z[(size_t)row * 32 + lane]    = dv * zz;
    }
}

// ---------------- layer2: slot-parallel agg(z) + log_softmax -----------------
// warp per row. q=lane&7 (float4 of 32-wide z row), slot=lane>>3: 4 edges
// in flight, one 128B wavefront per edge. float4 softmax, float4 store.
__global__ void __launch_bounds__(512) k_layer2(float* __restrict__ out, int N) {
    int gt = blockIdx.x * blockDim.x + threadIdx.x;
    int row = gt >> 5;
    if (row >= N) return;
    int lane = gt & 31;
    int q = lane & 7, slot = lane >> 3;
    int s = g_rps[row];
    int e = g_rps[row + 1];
    const float4* Z = (const float4*)g_z;
    float4 acc = make_float4(0.f, 0.f, 0.f, 0.f);
    for (int p = s + slot; p < e; p += 4) {
        int2 ce = g_csr[p];
        float nv = __int_as_float(ce.y);
        float4 v = Z[(size_t)ce.x * 8 + q];
        acc.x = fmaf(nv, v.x, acc.x);
        acc.y = fmaf(nv, v.y, acc.y);
        acc.z = fmaf(nv, v.z, acc.z);
        acc.w = fmaf(nv, v.w, acc.w);
    }
    #pragma unroll
    for (int d = 8; d < 32; d <<= 1) {
        acc.x += __shfl_xor_sync(0xffffffffu, acc.x, d);
        acc.y += __shfl_xor_sync(0xffffffffu, acc.y, d);
        acc.z += __shfl_xor_sync(0xffffffffu, acc.z, d);
        acc.w += __shfl_xor_sync(0xffffffffu, acc.w, d);
    }
    float dv = g_dinv[row];
    float4 sv = ((const float4*)g_self)[(size_t)row * 8 + q];
    float4 val;
    val.x = sv.x + dv * acc.x;
    val.y = sv.y + dv * acc.y;
    val.z = sv.z + dv * acc.z;
    val.w = sv.w + dv * acc.w;

    float m = fmaxf(fmaxf(val.x, val.y), fmaxf(val.z, val.w));
    #pragma unroll
    for (int d = 1; d < 8; d <<= 1) m = fmaxf(m, __shfl_xor_sync(0xffffffffu, m, d));
    float sum = __expf(val.x - m) + __expf(val.y - m)
              + __expf(val.z - m) + __expf(val.w - m);
    #pragma unroll
    for (int d = 1; d < 8; d <<= 1) sum += __shfl_xor_sync(0xffffffffu, sum, d);
    float ls = m + __logf(sum);
    if (lane < 8) {
        float4 o;
        o.x = val.x - ls; o.y = val.y - ls; o.z = val.z - ls; o.w = val.w - ls;
        ((float4*)out)[(size_t)row * 8 + q] = o;
    }
}

// ---------------- launcher ----------------------------------------------------
extern "C" void kernel_launch(void* const* d_in, const int* in_sizes, int n_in,
                              void* d_out, int out_size) {
    const float* x   = (const float*)d_in[0];
    const void*  ei  = d_in[1];
    const float* ew  = (const float*)d_in[2];
    const float* W10 = (const float*)d_in[3];
    const float* W11 = (const float*)d_in[4];
    const float* b1  = (const float*)d_in[5];
    const float* W20 = (const float*)d_in[6];
    const float* W21 = (const float*)d_in[7];
    const float* b2  = (const float*)d_in[8];
    float* out = (float*)d_out;

    int N = in_sizes[0] / 128;
    int E = in_sizes[2];
    int NB = (N + 2047) / 2048;

    k_build<<<NBLK, 1024>>>(ei, ew, N, E, NB);
    k_gemm1<<<(N + 63) / 64, 512>>>(x, W10, W11, N);
    k_layer1<<<296, 512>>>(b1, W20, W21, b2, N);
    k_layer2<<<(N * 32 + 511) / 512, 512>>>(out, N);
}